// round 4
// baseline (speedup 1.0000x reference)
#include <cuda_runtime.h>
#include <cstdint>

// ---------------------------------------------------------------------------
// SPNet fused single-kernel, v3.
//
// Round-3 lesson: the 64-reg cap (launch_bounds(256,4)) forced spills of the
// gather path's logit registers -> load serialization -> 2.3 TB/s. Round-1's
// standalone gather (96 regs, float4, 2 blocks/SM) ran at 5.6 TB/s. So:
// launch_bounds(256,2) (<=128 regs) + float4 gather path = round-1 code
// shape inside the megakernel, with conv overlapped via flags.
// ---------------------------------------------------------------------------

#define BATCH    16
#define HW       160000         // 400*400
#define HW4      40000          // float4 per plane
#define GB_PER_B 157            // ceil(40000/256)
#define NCONVBLK 64
#define NTHREADS 256

__device__ float    g_h1[BATCH * 6  * 64 * 64];
__device__ float    g_h2[BATCH * 12 * 32 * 32];
__device__ float    g_pal[BATCH * 48];
__device__ unsigned g_flags[48];   // [0:16) conv1 count, [16:32) conv2 count, [32:48) pal ready

__device__ __forceinline__ float leaky(float v) {
    return (v >= 0.f) ? v : 0.01f * v;
}

__global__ void __launch_bounds__(NTHREADS, 2)
spnet_fused_kernel(const float* __restrict__ x,
                   const float* __restrict__ logits,
                   const float* __restrict__ w1, const float* __restrict__ b1,
                   const float* __restrict__ w2, const float* __restrict__ b2,
                   const float* __restrict__ w3, const float* __restrict__ b3,
                   const float* __restrict__ w4, const float* __restrict__ b4,
                   const float* __restrict__ w5, const float* __restrict__ b5,
                   const float* __restrict__ w6, const float* __restrict__ b6,
                   float* __restrict__ out) {
    const int bid = blockIdx.x;
    const int tid = threadIdx.x;

    // =====================================================================
    // CONV PATH: blocks 0..63. b = bid>>2 (batch), q = bid&3 (quarter).
    // =====================================================================
    if (bid < NCONVBLK) {
        const int b = bid >> 2;
        const int q = bid & 3;

        __shared__ float sw1[162], sb1[6];
        __shared__ float sw2[648], sb2[12];
        __shared__ float sw3[1296], sb3[12];
        __shared__ float sw4[1296], sb4[12];
        __shared__ float sw5[648], sb5[6];
        __shared__ float sw6[18], sb6[3];
        __shared__ float h3[12 * 16 * 16];
        __shared__ float h4[12 * 8 * 8];
        __shared__ float h5[6 * 16];

        for (int i = tid; i < 162; i += NTHREADS) sw1[i] = w1[i];
        for (int i = tid; i < 648; i += NTHREADS) { sw2[i] = w2[i]; sw5[i] = w5[i]; }
        for (int i = tid; i < 1296; i += NTHREADS) { sw3[i] = w3[i]; sw4[i] = w4[i]; }
        if (tid < 18) sw6[tid] = w6[tid];
        if (tid < 12) { sb2[tid] = b2[tid]; sb3[tid] = b3[tid]; sb4[tid] = b4[tid]; }
        if (tid < 6)  { sb1[tid] = b1[tid]; sb5[tid] = b5[tid]; }
        if (tid < 3)  sb6[tid] = b6[tid];
        __syncthreads();

        // ---- conv1, quarter q: h1 rows [q*16, q*16+16) x cols [0,64) ----
        for (int pos = tid; pos < 1024; pos += NTHREADS) {
            const int i = q * 16 + (pos >> 6);
            const int j = pos & 63;
            float acc[6];
#pragma unroll
            for (int oc = 0; oc < 6; oc++) acc[oc] = sb1[oc];
#pragma unroll
            for (int ic = 0; ic < 3; ic++) {
                const float* xp = x + (size_t)(b * 3 + ic) * HW;
#pragma unroll
                for (int di = 0; di < 3; di++) {
                    const int yi = 2 * i + di - 1;
#pragma unroll
                    for (int dj = 0; dj < 3; dj++) {
                        const int yj = 2 * j + dj - 1;
                        float v = 0.f;
                        if (yi >= 0 && yj >= 0) v = xp[yi * 400 + yj];
#pragma unroll
                        for (int oc = 0; oc < 6; oc++)
                            acc[oc] = fmaf(sw1[(oc * 3 + ic) * 9 + di * 3 + dj], v, acc[oc]);
                    }
                }
            }
#pragma unroll
            for (int oc = 0; oc < 6; oc++)
                g_h1[((b * 6 + oc) * 64 + i) * 64 + j] = leaky(acc[oc]);
        }
        __threadfence();
        __syncthreads();
        if (tid == 0) atomicAdd(&g_flags[b], 1u);

        if (tid == 0) {
            while (atomicAdd(&g_flags[b], 0u) < 4u) __nanosleep(64);
            __threadfence();
        }
        __syncthreads();

        // ---- conv2, quarter q: rows [q*8, q*8+8) x cols [0,32), 12 oc ----
        {
            const int i = q * 8 + (tid >> 5);
            const int j = tid & 31;
            const float* h1b = g_h1 + (size_t)b * 6 * 64 * 64;
            float acc[12];
#pragma unroll
            for (int oc = 0; oc < 12; oc++) acc[oc] = sb2[oc];
#pragma unroll
            for (int ic = 0; ic < 6; ic++) {
#pragma unroll
                for (int di = 0; di < 3; di++) {
                    const int yi = 2 * i + di - 1;
#pragma unroll
                    for (int dj = 0; dj < 3; dj++) {
                        const int yj = 2 * j + dj - 1;
                        float v = 0.f;
                        if (yi >= 0 && yj >= 0) v = h1b[(ic * 64 + yi) * 64 + yj];
#pragma unroll
                        for (int oc = 0; oc < 12; oc++)
                            acc[oc] = fmaf(sw2[(oc * 6 + ic) * 9 + di * 3 + dj], v, acc[oc]);
                    }
                }
            }
#pragma unroll
            for (int oc = 0; oc < 12; oc++)
                g_h2[((b * 12 + oc) * 32 + i) * 32 + j] = leaky(acc[oc]);
        }
        __threadfence();
        __syncthreads();
        if (tid == 0) atomicAdd(&g_flags[16 + b], 1u);

        if (q != 0) return;   // only quarter-0 runs the tail

        if (tid == 0) {
            while (atomicAdd(&g_flags[16 + b], 0u) < 4u) __nanosleep(64);
            __threadfence();
        }
        __syncthreads();

        // ---- conv3: h2 -> h3[12,16,16]. 256 positions, 12 oc ----
        {
            const int i = tid >> 4;
            const int j = tid & 15;
            const float* h2b = g_h2 + (size_t)b * 12 * 32 * 32;
            float acc[12];
#pragma unroll
            for (int oc = 0; oc < 12; oc++) acc[oc] = sb3[oc];
            for (int ic = 0; ic < 12; ic++) {
#pragma unroll
                for (int di = 0; di < 3; di++) {
                    const int yi = 2 * i + di - 1;
#pragma unroll
                    for (int dj = 0; dj < 3; dj++) {
                        const int yj = 2 * j + dj - 1;
                        float v = 0.f;
                        if (yi >= 0 && yj >= 0) v = h2b[(ic * 32 + yi) * 32 + yj];
#pragma unroll
                        for (int oc = 0; oc < 12; oc++)
                            acc[oc] = fmaf(sw3[(oc * 12 + ic) * 9 + di * 3 + dj], v, acc[oc]);
                    }
                }
            }
#pragma unroll
            for (int oc = 0; oc < 12; oc++)
                h3[(oc * 16 + i) * 16 + j] = leaky(acc[oc]);
        }
        __syncthreads();

        // ---- conv4: h3 -> h4[12,8,8]. 64 threads, 12 oc ----
        if (tid < 64) {
            const int i = tid >> 3;
            const int j = tid & 7;
            float acc[12];
#pragma unroll
            for (int oc = 0; oc < 12; oc++) acc[oc] = sb4[oc];
            for (int ic = 0; ic < 12; ic++) {
#pragma unroll
                for (int di = 0; di < 3; di++) {
                    const int yi = 2 * i + di - 1;
#pragma unroll
                    for (int dj = 0; dj < 3; dj++) {
                        const int yj = 2 * j + dj - 1;
                        float v = 0.f;
                        if (yi >= 0 && yj >= 0) v = h3[(ic * 16 + yi) * 16 + yj];
#pragma unroll
                        for (int oc = 0; oc < 12; oc++)
                            acc[oc] = fmaf(sw4[(oc * 12 + ic) * 9 + di * 3 + dj], v, acc[oc]);
                    }
                }
            }
#pragma unroll
            for (int oc = 0; oc < 12; oc++)
                h4[(oc * 8 + i) * 8 + j] = leaky(acc[oc]);
        }
        __syncthreads();

        // ---- conv5: h4 -> h5[6,4,4]. 96 threads ----
        if (tid < 96) {
            const int oc = tid >> 4;
            const int p  = tid & 15;
            const int i  = p >> 2;
            const int jj = p & 3;
            float acc = sb5[oc];
            for (int ic = 0; ic < 12; ic++) {
#pragma unroll
                for (int di = 0; di < 3; di++) {
                    const int yi = 2 * i + di - 1;
#pragma unroll
                    for (int dj = 0; dj < 3; dj++) {
                        const int yj = 2 * jj + dj - 1;
                        float v = 0.f;
                        if (yi >= 0 && yj >= 0) v = h4[(ic * 8 + yi) * 8 + yj];
                        acc = fmaf(sw5[(oc * 12 + ic) * 9 + di * 3 + dj], v, acc);
                    }
                }
            }
            h5[oc * 16 + p] = leaky(acc);
        }
        __syncthreads();

        // ---- conv6 (1x1) + relu -> g_pal; publish ----
        if (tid < 48) {
            const int c = tid >> 4;
            const int k = tid & 15;
            float acc = sb6[c];
#pragma unroll
            for (int ic = 0; ic < 6; ic++)
                acc = fmaf(sw6[c * 6 + ic], h5[ic * 16 + k], acc);
            g_pal[b * 48 + c * 16 + k] = fmaxf(acc, 0.f);
            __threadfence();
        }
        __syncthreads();
        if (tid == 0) atomicExch(&g_flags[32 + b], 1u);
        return;
    }

    // =====================================================================
    // GATHER PATH: float4 (4 px per thread), round-1 code shape.
    // Issue all 16 loads first, compute max, wait for palette, accumulate.
    // =====================================================================
    const int gid = bid - NCONVBLK;
    const int b   = gid / GB_PER_B;
    const int blk = gid - b * GB_PER_B;
    const int p   = blk * NTHREADS + tid;          // float4 index in image
    const bool act = (p < HW4);

    __shared__ float spal[48];

    float4 l[16];
    float4 mx = make_float4(0.f, 0.f, 0.f, 0.f);

    if (act) {
        const float4* lg = reinterpret_cast<const float4*>(logits)
                           + (size_t)b * 16 * HW4 + p;
#pragma unroll
        for (int k = 0; k < 16; k++) l[k] = lg[(size_t)k * HW4];

        mx = l[0];
#pragma unroll
        for (int k = 1; k < 16; k++) {
            mx.x = fmaxf(mx.x, l[k].x);
            mx.y = fmaxf(mx.y, l[k].y);
            mx.z = fmaxf(mx.z, l[k].z);
            mx.w = fmaxf(mx.w, l[k].w);
        }
    }

    if (tid == 0) {
        while (atomicAdd(&g_flags[32 + b], 0u) == 0u) __nanosleep(128);
        __threadfence();
    }
    __syncthreads();
    if (tid < 48) spal[tid] = __ldcg(&g_pal[b * 48 + tid]);
    __syncthreads();

    if (!act) return;

    float4 a0 = make_float4(0.f, 0.f, 0.f, 0.f);
    float4 a1 = a0, a2 = a0;

#pragma unroll
    for (int k = 0; k < 16; k++) {
        const float p0 = spal[k];
        const float p1 = spal[16 + k];
        const float p2 = spal[32 + k];

        const float mxk = (l[k].x == mx.x) ? 1.f : 0.f;
        const float myk = (l[k].y == mx.y) ? 1.f : 0.f;
        const float mzk = (l[k].z == mx.z) ? 1.f : 0.f;
        const float mwk = (l[k].w == mx.w) ? 1.f : 0.f;

        a0.x = fmaf(mxk, p0, a0.x); a0.y = fmaf(myk, p0, a0.y);
        a0.z = fmaf(mzk, p0, a0.z); a0.w = fmaf(mwk, p0, a0.w);
        a1.x = fmaf(mxk, p1, a1.x); a1.y = fmaf(myk, p1, a1.y);
        a1.z = fmaf(mzk, p1, a1.z); a1.w = fmaf(mwk, p1, a1.w);
        a2.x = fmaf(mxk, p2, a2.x); a2.y = fmaf(myk, p2, a2.y);
        a2.z = fmaf(mzk, p2, a2.z); a2.w = fmaf(mwk, p2, a2.w);
    }

    float4* o = reinterpret_cast<float4*>(out) + (size_t)(b * 3) * HW4 + p;
    o[0]               = a0;
    o[HW4]             = a1;
    o[2 * (size_t)HW4] = a2;
}

// ---------------------------------------------------------------------------
extern "C" void kernel_launch(void* const* d_in, const int* in_sizes, int n_in,
                              void* d_out, int out_size) {
    (void)in_sizes; (void)n_in; (void)out_size;
    const float* x  = (const float*)d_in[0];
    const float* bl = (const float*)d_in[1];
    const float* w1 = (const float*)d_in[2];
    const float* b1 = (const float*)d_in[3];
    const float* w2 = (const float*)d_in[4];
    const float* b2 = (const float*)d_in[5];
    const float* w3 = (const float*)d_in[6];
    const float* b3 = (const float*)d_in[7];
    const float* w4 = (const float*)d_in[8];
    const float* b4 = (const float*)d_in[9];
    const float* w5 = (const float*)d_in[10];
    const float* b5 = (const float*)d_in[11];
    const float* w6 = (const float*)d_in[12];
    const float* b6 = (const float*)d_in[13];
    float* out = (float*)d_out;

    void* flags_ptr = nullptr;
    cudaGetSymbolAddress(&flags_ptr, g_flags);
    cudaMemsetAsync(flags_ptr, 0, 48 * sizeof(unsigned));

    const int grid = NCONVBLK + BATCH * GB_PER_B;   // 64 + 2512
    spnet_fused_kernel<<<grid, NTHREADS>>>(x, bl,
                                           w1, b1, w2, b2, w3, b3,
                                           w4, b4, w5, b5, w6, b6, out);
}

// round 5
// speedup vs baseline: 1.2605x; 1.2605x over previous
#include <cuda_runtime.h>
#include <cstdint>

// ---------------------------------------------------------------------------
// SPNet, v4: conv+mask kernel, then paint kernel.
//
// Round-4 lesson: gather steady-state was fine; the killer was wave-1 gather
// blocks spinning ~30us on the palette flag (conv critical path) while
// holding SM slots. Fix: gather is split into a palette-independent MASK pass
// (argmax tie bitmask, runs at full HBM rate immediately, conv hidden under
// it in the same kernel) and a tiny PAINT pass in a second kernel that gets
// the palette for free via stream ordering. Nobody waits on anybody.
// ---------------------------------------------------------------------------

#define BATCH    16
#define HW       160000         // 400*400
#define HW4      40000          // float4 per plane
#define GB_PER_B 157            // ceil(40000/256)
#define NCONVBLK 64
#define NTHREADS 256

__device__ float              g_h1[BATCH * 6  * 64 * 64];
__device__ float              g_h2[BATCH * 12 * 32 * 32];
__device__ float              g_pal[BATCH * 48];
__device__ unsigned long long g_mask[BATCH * HW4];   // 16 bits per px, 4 px per entry
__device__ unsigned           g_flags[48];           // conv1 count, conv2 count (palette needs no flag)

__device__ __forceinline__ float leaky(float v) {
    return (v >= 0.f) ? v : 0.01f * v;
}

// ===========================================================================
// Kernel 1: blocks 0..63 conv pipeline, blocks 64.. logit->tie-mask.
// ===========================================================================
__global__ void __launch_bounds__(NTHREADS, 2)
spnet_mask_kernel(const float* __restrict__ x,
                  const float* __restrict__ logits,
                  const float* __restrict__ w1, const float* __restrict__ b1,
                  const float* __restrict__ w2, const float* __restrict__ b2,
                  const float* __restrict__ w3, const float* __restrict__ b3,
                  const float* __restrict__ w4, const float* __restrict__ b4,
                  const float* __restrict__ w5, const float* __restrict__ b5,
                  const float* __restrict__ w6, const float* __restrict__ b6) {
    const int bid = blockIdx.x;
    const int tid = threadIdx.x;

    // ---------------------------------------------------------------------
    // CONV PATH (b = bid>>2, q = bid&3) — unchanged from round 4.
    // ---------------------------------------------------------------------
    if (bid < NCONVBLK) {
        const int b = bid >> 2;
        const int q = bid & 3;

        __shared__ float sw1[162], sb1[6];
        __shared__ float sw2[648], sb2[12];
        __shared__ float sw3[1296], sb3[12];
        __shared__ float sw4[1296], sb4[12];
        __shared__ float sw5[648], sb5[6];
        __shared__ float sw6[18], sb6[3];
        __shared__ float h3[12 * 16 * 16];
        __shared__ float h4[12 * 8 * 8];
        __shared__ float h5[6 * 16];

        for (int i = tid; i < 162; i += NTHREADS) sw1[i] = w1[i];
        for (int i = tid; i < 648; i += NTHREADS) { sw2[i] = w2[i]; sw5[i] = w5[i]; }
        for (int i = tid; i < 1296; i += NTHREADS) { sw3[i] = w3[i]; sw4[i] = w4[i]; }
        if (tid < 18) sw6[tid] = w6[tid];
        if (tid < 12) { sb2[tid] = b2[tid]; sb3[tid] = b3[tid]; sb4[tid] = b4[tid]; }
        if (tid < 6)  { sb1[tid] = b1[tid]; sb5[tid] = b5[tid]; }
        if (tid < 3)  sb6[tid] = b6[tid];
        __syncthreads();

        // conv1, quarter q
        for (int pos = tid; pos < 1024; pos += NTHREADS) {
            const int i = q * 16 + (pos >> 6);
            const int j = pos & 63;
            float acc[6];
#pragma unroll
            for (int oc = 0; oc < 6; oc++) acc[oc] = sb1[oc];
#pragma unroll
            for (int ic = 0; ic < 3; ic++) {
                const float* xp = x + (size_t)(b * 3 + ic) * HW;
#pragma unroll
                for (int di = 0; di < 3; di++) {
                    const int yi = 2 * i + di - 1;
#pragma unroll
                    for (int dj = 0; dj < 3; dj++) {
                        const int yj = 2 * j + dj - 1;
                        float v = 0.f;
                        if (yi >= 0 && yj >= 0) v = xp[yi * 400 + yj];
#pragma unroll
                        for (int oc = 0; oc < 6; oc++)
                            acc[oc] = fmaf(sw1[(oc * 3 + ic) * 9 + di * 3 + dj], v, acc[oc]);
                    }
                }
            }
#pragma unroll
            for (int oc = 0; oc < 6; oc++)
                g_h1[((b * 6 + oc) * 64 + i) * 64 + j] = leaky(acc[oc]);
        }
        __threadfence();
        __syncthreads();
        if (tid == 0) atomicAdd(&g_flags[b], 1u);

        if (tid == 0) {
            while (atomicAdd(&g_flags[b], 0u) < 4u) __nanosleep(64);
            __threadfence();
        }
        __syncthreads();

        // conv2, quarter q
        {
            const int i = q * 8 + (tid >> 5);
            const int j = tid & 31;
            const float* h1b = g_h1 + (size_t)b * 6 * 64 * 64;
            float acc[12];
#pragma unroll
            for (int oc = 0; oc < 12; oc++) acc[oc] = sb2[oc];
#pragma unroll
            for (int ic = 0; ic < 6; ic++) {
#pragma unroll
                for (int di = 0; di < 3; di++) {
                    const int yi = 2 * i + di - 1;
#pragma unroll
                    for (int dj = 0; dj < 3; dj++) {
                        const int yj = 2 * j + dj - 1;
                        float v = 0.f;
                        if (yi >= 0 && yj >= 0) v = h1b[(ic * 64 + yi) * 64 + yj];
#pragma unroll
                        for (int oc = 0; oc < 12; oc++)
                            acc[oc] = fmaf(sw2[(oc * 6 + ic) * 9 + di * 3 + dj], v, acc[oc]);
                    }
                }
            }
#pragma unroll
            for (int oc = 0; oc < 12; oc++)
                g_h2[((b * 12 + oc) * 32 + i) * 32 + j] = leaky(acc[oc]);
        }
        __threadfence();
        __syncthreads();
        if (tid == 0) atomicAdd(&g_flags[16 + b], 1u);

        if (q != 0) return;

        if (tid == 0) {
            while (atomicAdd(&g_flags[16 + b], 0u) < 4u) __nanosleep(64);
            __threadfence();
        }
        __syncthreads();

        // conv3
        {
            const int i = tid >> 4;
            const int j = tid & 15;
            const float* h2b = g_h2 + (size_t)b * 12 * 32 * 32;
            float acc[12];
#pragma unroll
            for (int oc = 0; oc < 12; oc++) acc[oc] = sb3[oc];
            for (int ic = 0; ic < 12; ic++) {
#pragma unroll
                for (int di = 0; di < 3; di++) {
                    const int yi = 2 * i + di - 1;
#pragma unroll
                    for (int dj = 0; dj < 3; dj++) {
                        const int yj = 2 * j + dj - 1;
                        float v = 0.f;
                        if (yi >= 0 && yj >= 0) v = h2b[(ic * 32 + yi) * 32 + yj];
#pragma unroll
                        for (int oc = 0; oc < 12; oc++)
                            acc[oc] = fmaf(sw3[(oc * 12 + ic) * 9 + di * 3 + dj], v, acc[oc]);
                    }
                }
            }
#pragma unroll
            for (int oc = 0; oc < 12; oc++)
                h3[(oc * 16 + i) * 16 + j] = leaky(acc[oc]);
        }
        __syncthreads();

        // conv4
        if (tid < 64) {
            const int i = tid >> 3;
            const int j = tid & 7;
            float acc[12];
#pragma unroll
            for (int oc = 0; oc < 12; oc++) acc[oc] = sb4[oc];
            for (int ic = 0; ic < 12; ic++) {
#pragma unroll
                for (int di = 0; di < 3; di++) {
                    const int yi = 2 * i + di - 1;
#pragma unroll
                    for (int dj = 0; dj < 3; dj++) {
                        const int yj = 2 * j + dj - 1;
                        float v = 0.f;
                        if (yi >= 0 && yj >= 0) v = h3[(ic * 16 + yi) * 16 + yj];
#pragma unroll
                        for (int oc = 0; oc < 12; oc++)
                            acc[oc] = fmaf(sw4[(oc * 12 + ic) * 9 + di * 3 + dj], v, acc[oc]);
                    }
                }
            }
#pragma unroll
            for (int oc = 0; oc < 12; oc++)
                h4[(oc * 8 + i) * 8 + j] = leaky(acc[oc]);
        }
        __syncthreads();

        // conv5
        if (tid < 96) {
            const int oc = tid >> 4;
            const int p  = tid & 15;
            const int i  = p >> 2;
            const int jj = p & 3;
            float acc = sb5[oc];
            for (int ic = 0; ic < 12; ic++) {
#pragma unroll
                for (int di = 0; di < 3; di++) {
                    const int yi = 2 * i + di - 1;
#pragma unroll
                    for (int dj = 0; dj < 3; dj++) {
                        const int yj = 2 * jj + dj - 1;
                        float v = 0.f;
                        if (yi >= 0 && yj >= 0) v = h4[(ic * 8 + yi) * 8 + yj];
                        acc = fmaf(sw5[(oc * 12 + ic) * 9 + di * 3 + dj], v, acc);
                    }
                }
            }
            h5[oc * 16 + p] = leaky(acc);
        }
        __syncthreads();

        // conv6 (1x1) + relu -> g_pal (paint kernel is stream-ordered after us)
        if (tid < 48) {
            const int c = tid >> 4;
            const int k = tid & 15;
            float acc = sb6[c];
#pragma unroll
            for (int ic = 0; ic < 6; ic++)
                acc = fmaf(sw6[c * 6 + ic], h5[ic * 16 + k], acc);
            g_pal[b * 48 + c * 16 + k] = fmaxf(acc, 0.f);
        }
        return;
    }

    // ---------------------------------------------------------------------
    // MASK PATH: 4 px per thread (float4). No waiting, pure streaming.
    // ---------------------------------------------------------------------
    const int gid = bid - NCONVBLK;
    const int b   = gid / GB_PER_B;
    const int blk = gid - b * GB_PER_B;
    const int p   = blk * NTHREADS + tid;
    if (p >= HW4) return;

    const float4* lg = reinterpret_cast<const float4*>(logits)
                       + (size_t)b * 16 * HW4 + p;

    float4 l[16];
#pragma unroll
    for (int k = 0; k < 16; k++) l[k] = __ldcs(lg + (size_t)k * HW4);

    float4 mx = l[0];
#pragma unroll
    for (int k = 1; k < 16; k++) {
        mx.x = fmaxf(mx.x, l[k].x);
        mx.y = fmaxf(mx.y, l[k].y);
        mx.z = fmaxf(mx.z, l[k].z);
        mx.w = fmaxf(mx.w, l[k].w);
    }

    unsigned mA = 0, mB = 0, mC = 0, mD = 0;
#pragma unroll
    for (int k = 0; k < 16; k++) {
        mA |= (l[k].x == mx.x) ? (1u << k) : 0u;
        mB |= (l[k].y == mx.y) ? (1u << k) : 0u;
        mC |= (l[k].z == mx.z) ? (1u << k) : 0u;
        mD |= (l[k].w == mx.w) ? (1u << k) : 0u;
    }

    const unsigned long long m =
        (unsigned long long)mA
        | ((unsigned long long)mB << 16)
        | ((unsigned long long)mC << 32)
        | ((unsigned long long)mD << 48);
    g_mask[(size_t)b * HW4 + p] = m;
}

// ===========================================================================
// Kernel 2: paint. mask (L2-warm) + palette -> output. No flags needed.
// ===========================================================================
__global__ void __launch_bounds__(NTHREADS)
spnet_paint_kernel(float* __restrict__ out) {
    const int gid = blockIdx.x;
    const int b   = gid / GB_PER_B;
    const int blk = gid - b * GB_PER_B;
    const int p   = blk * NTHREADS + threadIdx.x;

    __shared__ float spal[48];
    if (threadIdx.x < 48) spal[threadIdx.x] = g_pal[b * 48 + threadIdx.x];
    __syncthreads();

    if (p >= HW4) return;

    const unsigned long long m = g_mask[(size_t)b * HW4 + p];

    float r0[4], r1[4], r2[4];
#pragma unroll
    for (int px = 0; px < 4; px++) {
        const unsigned bits = (unsigned)((m >> (16 * px)) & 0xFFFFull);
        float s0 = 0.f, s1 = 0.f, s2 = 0.f;
#pragma unroll
        for (int k = 0; k < 16; k++) {
            const float f = (float)((bits >> k) & 1u);
            s0 = fmaf(f, spal[k],      s0);
            s1 = fmaf(f, spal[16 + k], s1);
            s2 = fmaf(f, spal[32 + k], s2);
        }
        r0[px] = s0; r1[px] = s1; r2[px] = s2;
    }

    float4* o = reinterpret_cast<float4*>(out) + (size_t)(b * 3) * HW4 + p;
    o[0]               = make_float4(r0[0], r0[1], r0[2], r0[3]);
    o[HW4]             = make_float4(r1[0], r1[1], r1[2], r1[3]);
    o[2 * (size_t)HW4] = make_float4(r2[0], r2[1], r2[2], r2[3]);
}

// ---------------------------------------------------------------------------
extern "C" void kernel_launch(void* const* d_in, const int* in_sizes, int n_in,
                              void* d_out, int out_size) {
    (void)in_sizes; (void)n_in; (void)out_size;
    const float* x  = (const float*)d_in[0];
    const float* bl = (const float*)d_in[1];
    const float* w1 = (const float*)d_in[2];
    const float* b1 = (const float*)d_in[3];
    const float* w2 = (const float*)d_in[4];
    const float* b2 = (const float*)d_in[5];
    const float* w3 = (const float*)d_in[6];
    const float* b3 = (const float*)d_in[7];
    const float* w4 = (const float*)d_in[8];
    const float* b4 = (const float*)d_in[9];
    const float* w5 = (const float*)d_in[10];
    const float* b5 = (const float*)d_in[11];
    const float* w6 = (const float*)d_in[12];
    const float* b6 = (const float*)d_in[13];
    float* out = (float*)d_out;

    void* flags_ptr = nullptr;
    cudaGetSymbolAddress(&flags_ptr, g_flags);
    cudaMemsetAsync(flags_ptr, 0, 48 * sizeof(unsigned));

    spnet_mask_kernel<<<NCONVBLK + BATCH * GB_PER_B, NTHREADS>>>(
        x, bl, w1, b1, w2, b2, w3, b3, w4, b4, w5, b5, w6, b6);
    spnet_paint_kernel<<<BATCH * GB_PER_B, NTHREADS>>>(out);
}